// round 2
// baseline (speedup 1.0000x reference)
#include <cuda_runtime.h>
#include <math.h>

#define N_NODES 50000
#define F_IN 128
#define H 64
#define HEADS 4
#define E_MAX 800000
#define NH (N_NODES * H)

// ---------------- scratch (static device memory; no allocs) ----------------
__device__ float g_xw[NH];              // x @ W1
__device__ float g_deg[N_NODES];        // count of incoming (no self loop)
__device__ float g_dinv[N_NODES];       // rsqrt(deg+1)
__device__ float g_h1[NH];              // GCN output (accum then relu'd)
__device__ float g_hg[N_NODES * HEADS * H];  // GAT transformed feats
__device__ float g_asrc[N_NODES * HEADS];
__device__ float g_adst[N_NODES * HEADS];
__device__ float g_eself[N_NODES * HEADS];
__device__ float g_emax[N_NODES * HEADS];
__device__ float g_exself[N_NODES * HEADS];
__device__ float g_esum[N_NODES * HEADS];
__device__ float g_ex[E_MAX * HEADS];   // per-edge exp, then alpha*0.25
__device__ float g_h2[NH];              // GAT output
__device__ float g_sagg[NH];            // SAGE neighbor sum

__device__ __forceinline__ float leaky(float v) { return v > 0.f ? v : 0.2f * v; }

__device__ __forceinline__ void atomicMaxF(float* addr, float v) {
    if (v >= 0.f) atomicMax((int*)addr, __float_as_int(v));
    else          atomicMin((unsigned int*)addr, __float_as_uint(v));
}

// ---------------- kernels ----------------

__global__ void k_zero() {
    int i = blockIdx.x * blockDim.x + threadIdx.x;
    if (i < NH) { g_h1[i] = 0.f; g_sagg[i] = 0.f; }
    if (i < N_NODES) g_deg[i] = 0.f;
}

// xw = x @ W1   (one block per node, 64 threads)
__global__ void k_xw(const float* __restrict__ x, const float* __restrict__ W1) {
    int n = blockIdx.x;
    int t = threadIdx.x;
    __shared__ float xs[F_IN];
    xs[t]      = x[n * F_IN + t];
    xs[t + 64] = x[n * F_IN + t + 64];
    __syncthreads();
    float acc = 0.f;
#pragma unroll 8
    for (int k = 0; k < F_IN; k++) acc += xs[k] * W1[k * H + t];
    g_xw[n * H + t] = acc;
}

__global__ void k_degcnt(const int* __restrict__ ei, int E) {
    int e = blockIdx.x * blockDim.x + threadIdx.x;
    if (e >= E) return;
    atomicAdd(&g_deg[ei[E + e]], 1.f);
}

__global__ void k_dinv() {
    int i = blockIdx.x * blockDim.x + threadIdx.x;
    if (i < N_NODES) g_dinv[i] = rsqrtf(g_deg[i] + 1.f);
}

// GCN edge scatter: h1[col] += dinv[row]*dinv[col]*xw[row]
__global__ void k_gcn_scatter(const int* __restrict__ ei, int E) {
    long long idx = (long long)blockIdx.x * blockDim.x + threadIdx.x;
    if (idx >= (long long)E * H) return;
    int e = (int)(idx >> 6), c = (int)(idx & 63);
    int r = ei[e], cl = ei[E + e];
    float nrm = g_dinv[r] * g_dinv[cl];
    atomicAdd(&g_h1[cl * H + c], nrm * g_xw[r * H + c]);
}

// + self-loop term + bias, relu
__global__ void k_gcn_final(const float* __restrict__ b1) {
    int idx = blockIdx.x * blockDim.x + threadIdx.x;
    if (idx >= NH) return;
    int n = idx >> 6, c = idx & 63;
    float d = g_dinv[n];
    float v = g_h1[idx] + d * d * g_xw[idx] + b1[c];
    g_h1[idx] = fmaxf(v, 0.f);
}

// hg = h1 @ Wg, plus per-node a_src/a_dst and self-loop logit init
__global__ void k_hg(const float* __restrict__ Wg,
                     const float* __restrict__ att_src,
                     const float* __restrict__ att_dst) {
    int n = blockIdx.x;
    int t = threadIdx.x;                 // 256 threads: h = t/64, c = t%64
    __shared__ float hs[H];
    __shared__ float ws_s[8], ws_d[8];
    if (t < H) hs[t] = g_h1[n * H + t];
    __syncthreads();
    float acc = 0.f;
#pragma unroll 8
    for (int k = 0; k < H; k++) acc += hs[k] * Wg[k * (HEADS * H) + t];
    g_hg[n * (HEADS * H) + t] = acc;
    float vs = acc * att_src[t];
    float vd = acc * att_dst[t];
#pragma unroll
    for (int off = 16; off > 0; off >>= 1) {
        vs += __shfl_down_sync(0xffffffffu, vs, off);
        vd += __shfl_down_sync(0xffffffffu, vd, off);
    }
    int w = t >> 5, lane = t & 31;
    if (lane == 0) { ws_s[w] = vs; ws_d[w] = vd; }
    __syncthreads();
    if (t < HEADS) {
        float as = ws_s[2 * t] + ws_s[2 * t + 1];
        float ad = ws_d[2 * t] + ws_d[2 * t + 1];
        g_asrc[n * HEADS + t] = as;
        g_adst[n * HEADS + t] = ad;
        float es = leaky(as + ad);
        g_eself[n * HEADS + t] = es;
        g_emax[n * HEADS + t]  = es;   // self loop always present
    }
}

__global__ void k_gat_max(const int* __restrict__ ei, int E) {
    long long idx = (long long)blockIdx.x * blockDim.x + threadIdx.x;
    if (idx >= (long long)E * HEADS) return;
    int e = (int)(idx >> 2), h = (int)(idx & 3);
    int r = ei[e], cl = ei[E + e];
    float v = leaky(g_asrc[r * HEADS + h] + g_adst[cl * HEADS + h]);
    atomicMaxF(&g_emax[cl * HEADS + h], v);
}

__global__ void k_esum_init() {
    int idx = blockIdx.x * blockDim.x + threadIdx.x;
    if (idx >= N_NODES * HEADS) return;
    float ex = expf(g_eself[idx] - g_emax[idx]);
    g_exself[idx] = ex;
    g_esum[idx]   = ex;
}

__global__ void k_gat_exp(const int* __restrict__ ei, int E) {
    long long idx = (long long)blockIdx.x * blockDim.x + threadIdx.x;
    if (idx >= (long long)E * HEADS) return;
    int e = (int)(idx >> 2), h = (int)(idx & 3);
    int r = ei[e], cl = ei[E + e];
    float v = leaky(g_asrc[r * HEADS + h] + g_adst[cl * HEADS + h]);
    float ex = expf(v - g_emax[cl * HEADS + h]);
    g_ex[idx] = ex;
    atomicAdd(&g_esum[cl * HEADS + h], ex);
}

// convert ex -> 0.25 * alpha  (one divide per (edge,head) instead of per element)
__global__ void k_alpha(const int* __restrict__ ei, int E) {
    long long idx = (long long)blockIdx.x * blockDim.x + threadIdx.x;
    if (idx >= (long long)E * HEADS) return;
    int e = (int)(idx >> 2), h = (int)(idx & 3);
    int cl = ei[E + e];
    g_ex[idx] = 0.25f * g_ex[idx] / g_esum[cl * HEADS + h];
}

// init h2 with self-loop contribution
__global__ void k_h2_init() {
    int idx = blockIdx.x * blockDim.x + threadIdx.x;
    if (idx >= NH) return;
    int n = idx >> 6, c = idx & 63;
    float acc = 0.f;
#pragma unroll
    for (int h = 0; h < HEADS; h++) {
        float a = g_exself[n * HEADS + h] / g_esum[n * HEADS + h];
        acc += a * g_hg[n * (HEADS * H) + h * H + c];
    }
    g_h2[idx] = 0.25f * acc;
}

__global__ void k_gat_scatter(const int* __restrict__ ei, int E) {
    long long idx = (long long)blockIdx.x * blockDim.x + threadIdx.x;
    if (idx >= (long long)E * H) return;
    int e = (int)(idx >> 6), c = (int)(idx & 63);
    int r = ei[e], cl = ei[E + e];
    const float* hgr = &g_hg[r * (HEADS * H) + c];
    float acc = 0.f;
#pragma unroll
    for (int h = 0; h < HEADS; h++)
        acc += g_ex[e * HEADS + h] * hgr[h * H];
    atomicAdd(&g_h2[cl * H + c], acc);
}

__global__ void k_gat_final(const float* __restrict__ bg) {
    int idx = blockIdx.x * blockDim.x + threadIdx.x;
    if (idx >= NH) return;
    int c = idx & 63;
    g_h2[idx] = fmaxf(g_h2[idx] + bg[c], 0.f);
}

__global__ void k_sage_scatter(const int* __restrict__ ei, int E) {
    long long idx = (long long)blockIdx.x * blockDim.x + threadIdx.x;
    if (idx >= (long long)E * H) return;
    int e = (int)(idx >> 6), c = (int)(idx & 63);
    int r = ei[e], cl = ei[E + e];
    atomicAdd(&g_sagg[cl * H + c], g_h2[r * H + c]);
}

// emb = mean_agg @ Wl + bl + h2 @ Wr; then both sigmoid heads. 64 thr/node.
__global__ void k_final(const float* __restrict__ Wl, const float* __restrict__ bl,
                        const float* __restrict__ Wr,
                        const float* __restrict__ a1_w, const float* __restrict__ a1_b,
                        const float* __restrict__ a2_w, const float* __restrict__ a2_b,
                        const float* __restrict__ r1_w, const float* __restrict__ r1_b,
                        const float* __restrict__ r2_w, const float* __restrict__ r2_b,
                        float* __restrict__ out) {
    int n = blockIdx.x;
    int t = threadIdx.x;
    __shared__ float m[H], hh[H], embS[H];
    float dg = fmaxf(g_deg[n], 1.f);
    m[t]  = g_sagg[n * H + t] / dg;
    hh[t] = g_h2[n * H + t];
    __syncthreads();
    float acc = bl[t];
#pragma unroll 8
    for (int k = 0; k < H; k++)
        acc += m[k] * Wl[k * H + t] + hh[k] * Wr[k * H + t];
    embS[t] = acc;
    out[n * H + t] = acc;
    __syncthreads();
    // warp 0 -> anomaly head, warp 1 -> risk head
    int w = t >> 5, lane = t & 31;
    const float* W1h = w ? r1_w : a1_w;
    const float* B1h = w ? r1_b : a1_b;
    const float* W2h = w ? r2_w : a2_w;
    const float* B2h = w ? r2_b : a2_b;
    float z = B1h[lane];
#pragma unroll 8
    for (int c = 0; c < H; c++) z += embS[c] * W1h[c * 32 + lane];
    z = fmaxf(z, 0.f) * W2h[lane];
#pragma unroll
    for (int off = 16; off > 0; off >>= 1)
        z += __shfl_down_sync(0xffffffffu, z, off);
    if (lane == 0) {
        float v = z + B2h[0];
        v = 1.f / (1.f + expf(-v));
        out[NH + w * N_NODES + n] = v;
    }
}

// ---------------- launch ----------------
extern "C" void kernel_launch(void* const* d_in, const int* in_sizes, int n_in,
                              void* d_out, int out_size) {
    const float*      x       = (const float*)d_in[0];
    const int*        ei      = (const int*)d_in[1];
    const float*      W1      = (const float*)d_in[2];
    const float*      b1      = (const float*)d_in[3];
    const float*      Wg      = (const float*)d_in[4];
    const float*      att_src = (const float*)d_in[5];
    const float*      att_dst = (const float*)d_in[6];
    const float*      bg      = (const float*)d_in[7];
    const float*      Wl      = (const float*)d_in[8];
    const float*      bl      = (const float*)d_in[9];
    const float*      Wr      = (const float*)d_in[10];
    const float*      a1_w    = (const float*)d_in[11];
    const float*      a1_b    = (const float*)d_in[12];
    const float*      a2_w    = (const float*)d_in[13];
    const float*      a2_b    = (const float*)d_in[14];
    const float*      r1_w    = (const float*)d_in[15];
    const float*      r1_b    = (const float*)d_in[16];
    const float*      r2_w    = (const float*)d_in[17];
    const float*      r2_b    = (const float*)d_in[18];
    float* out = (float*)d_out;

    int E = in_sizes[1] / 2;
    const int T = 256;
    long long e64 = (long long)E * H;
    long long e4  = (long long)E * HEADS;
    int gEH  = (int)((e64 + T - 1) / T);
    int gE4  = (int)((e4 + T - 1) / T);
    int gE   = (E + T - 1) / T;
    int gNH  = (NH + T - 1) / T;
    int gN4  = (N_NODES * HEADS + T - 1) / T;

    k_zero<<<gNH, T>>>();
    k_xw<<<N_NODES, 64>>>(x, W1);
    k_degcnt<<<gE, T>>>(ei, E);
    k_dinv<<<(N_NODES + T - 1) / T, T>>>();
    k_gcn_scatter<<<gEH, T>>>(ei, E);
    k_gcn_final<<<gNH, T>>>(b1);
    k_hg<<<N_NODES, 256>>>(Wg, att_src, att_dst);
    k_gat_max<<<gE4, T>>>(ei, E);
    k_esum_init<<<gN4, T>>>();
    k_gat_exp<<<gE4, T>>>(ei, E);
    k_alpha<<<gE4, T>>>(ei, E);
    k_h2_init<<<gNH, T>>>();
    k_gat_scatter<<<gEH, T>>>(ei, E);
    k_gat_final<<<gNH, T>>>(bg);
    k_sage_scatter<<<gEH, T>>>(ei, E);
    k_final<<<N_NODES, 64>>>(Wl, bl, Wr, a1_w, a1_b, a2_w, a2_b,
                             r1_w, r1_b, r2_w, r2_b, out);
}

// round 4
// speedup vs baseline: 2.0489x; 2.0489x over previous
#include <cuda_runtime.h>
#include <math.h>

#define N_NODES 50000
#define F_IN 128
#define H 64
#define HEADS 4
#define E_MAX 800000
#define NH (N_NODES * H)

// ---------------- scratch ----------------
__device__ float g_xw[NH];
__device__ float g_deg[N_NODES];
__device__ float g_dinv[N_NODES];
__device__ float g_h1[NH];
__device__ float g_hg[N_NODES * HEADS * H];
__device__ float g_asrc[N_NODES * HEADS];
__device__ float g_adst[N_NODES * HEADS];
__device__ float g_eself[N_NODES * HEADS];
__device__ float g_emax[N_NODES * HEADS];
__device__ float g_exself[N_NODES * HEADS];
__device__ float g_esum[N_NODES * HEADS];
__device__ float g_ex[E_MAX * HEADS];
__device__ float g_h2[NH];
__device__ float g_sagg[NH];

__device__ __forceinline__ float leaky(float v) { return v > 0.f ? v : 0.2f * v; }

__device__ __forceinline__ void atomicMaxF(float* addr, float v) {
    if (v >= 0.f) atomicMax((int*)addr, __float_as_int(v));
    else          atomicMin((unsigned int*)addr, __float_as_uint(v));
}

// sm_90+: vectorized reduction (4 floats, one LTS op)
__device__ __forceinline__ void red_add_v4(float* addr, float a, float b, float c, float d) {
    asm volatile("red.global.add.v4.f32 [%0], {%1, %2, %3, %4};"
                 :: "l"(addr), "f"(a), "f"(b), "f"(c), "f"(d) : "memory");
}

// ---------------- elementwise / small ----------------

__global__ void k_zero() {
    int i = blockIdx.x * blockDim.x + threadIdx.x;
    if (i < NH / 4) {
        ((float4*)g_h1)[i]   = make_float4(0.f, 0.f, 0.f, 0.f);
        ((float4*)g_sagg)[i] = make_float4(0.f, 0.f, 0.f, 0.f);
    }
    if (i < N_NODES / 4)
        ((float4*)g_deg)[i] = make_float4(0.f, 0.f, 0.f, 0.f);
}

__global__ void k_degcnt(const int* __restrict__ ei, int E) {
    int e = blockIdx.x * blockDim.x + threadIdx.x;
    if (e >= E) return;
    atomicAdd(&g_deg[ei[E + e]], 1.f);
}

__global__ void k_dinv() {
    int i = blockIdx.x * blockDim.x + threadIdx.x;
    if (i < N_NODES) g_dinv[i] = rsqrtf(g_deg[i] + 1.f);
}

// ---------------- dense: xw = x @ W1 (128->64), 64 nodes/block ----------------
#define XW_SMEM ((128 * 64 + 128 * 68) * 4)
__global__ __launch_bounds__(256) void k_xw(const float* __restrict__ x,
                                            const float* __restrict__ W1) {
    extern __shared__ float sm[];
    float* Ws = sm;              // [k][c] 128x64
    float* xs = sm + 128 * 64;   // [k][n] stride 68
    int t = threadIdx.x;
    int n0 = blockIdx.x * 64;

    const float4* W4 = (const float4*)W1;
    float4* Ws4 = (float4*)Ws;
#pragma unroll
    for (int i = 0; i < 8; i++) Ws4[t + 256 * i] = W4[t + 256 * i];

    int nl = t & 63, kq = t >> 6;          // kq 0..3
    if (n0 + nl < N_NODES) {
#pragma unroll
        for (int j = 0; j < 8; j++) {
            int chunk = kq * 8 + j;        // 0..31
            float4 v = *(const float4*)&x[(size_t)(n0 + nl) * F_IN + chunk * 4];
            int k = chunk * 4;
            xs[(k + 0) * 68 + nl] = v.x;
            xs[(k + 1) * 68 + nl] = v.y;
            xs[(k + 2) * 68 + nl] = v.z;
            xs[(k + 3) * 68 + nl] = v.w;
        }
    }
    __syncthreads();

    int cq = t & 15, nq = t >> 4;          // 4 cols x 4 nodes per thread
    float acc[4][4] = {};
#pragma unroll 4
    for (int k = 0; k < 128; k++) {
        float4 xv = *(const float4*)&xs[k * 68 + nq * 4];
        float4 wv = *(const float4*)&Ws[k * 64 + cq * 4];
        float xa[4] = {xv.x, xv.y, xv.z, xv.w};
        float wa[4] = {wv.x, wv.y, wv.z, wv.w};
#pragma unroll
        for (int i = 0; i < 4; i++)
#pragma unroll
            for (int j = 0; j < 4; j++) acc[i][j] += xa[i] * wa[j];
    }
#pragma unroll
    for (int i = 0; i < 4; i++) {
        int n = n0 + nq * 4 + i;
        if (n < N_NODES)
            *(float4*)&g_xw[n * 64 + cq * 4] =
                make_float4(acc[i][0], acc[i][1], acc[i][2], acc[i][3]);
    }
}

// ---------------- GCN scatter + final ----------------
__global__ void k_gcn_scatter(const int* __restrict__ ei, int E) {
    int idx = blockIdx.x * blockDim.x + threadIdx.x;
    if (idx >= E * 16) return;
    int e = idx >> 4, q = (idx & 15) * 4;
    int r = ei[e], cl = ei[E + e];
    float nrm = g_dinv[r] * g_dinv[cl];
    float4 v = *(const float4*)&g_xw[r * 64 + q];
    red_add_v4(&g_h1[cl * 64 + q], v.x * nrm, v.y * nrm, v.z * nrm, v.w * nrm);
}

__global__ void k_gcn_final(const float* __restrict__ b1) {
    int idx = blockIdx.x * blockDim.x + threadIdx.x;
    if (idx >= NH / 4) return;
    int n = idx >> 4, q = (idx & 15) * 4;
    float d = g_dinv[n]; float d2 = d * d;
    float4 h = ((const float4*)g_h1)[idx];
    float4 xw = ((const float4*)g_xw)[idx];
    float4 b = *(const float4*)&b1[q];
    h.x = fmaxf(h.x + d2 * xw.x + b.x, 0.f);
    h.y = fmaxf(h.y + d2 * xw.y + b.y, 0.f);
    h.z = fmaxf(h.z + d2 * xw.z + b.z, 0.f);
    h.w = fmaxf(h.w + d2 * xw.w + b.w, 0.f);
    ((float4*)g_h1)[idx] = h;
}

// ---------------- dense: hg = h1 @ Wg (64->256) + attention dots, 32 nodes/block ----------------
#define HG_SMEM ((64 * 256 + 64 * 36 + 256) * 4)
__global__ __launch_bounds__(512) void k_hg(const float* __restrict__ Wg,
                                            const float* __restrict__ att_src,
                                            const float* __restrict__ att_dst) {
    extern __shared__ float sm[];
    float* Ws = sm;                      // 64x256
    float* hs = sm + 64 * 256;           // [k][n] stride 36
    float* as_s = sm + 64 * 256 + 64 * 36;  // 128
    float* ad_s = as_s + 128;               // 128
    int t = threadIdx.x;
    int n0 = blockIdx.x * 32;

    const float4* W4 = (const float4*)Wg;
    float4* Ws4 = (float4*)Ws;
#pragma unroll
    for (int i = 0; i < 8; i++) Ws4[t + 512 * i] = W4[t + 512 * i];

    int nl = t & 31, kq = t >> 5;        // kq 0..15
    if (n0 + nl < N_NODES) {
        float4 v = *(const float4*)&g_h1[(n0 + nl) * 64 + kq * 4];
        int k = kq * 4;
        hs[(k + 0) * 36 + nl] = v.x;
        hs[(k + 1) * 36 + nl] = v.y;
        hs[(k + 2) * 36 + nl] = v.z;
        hs[(k + 3) * 36 + nl] = v.w;
    }
    if (t < 128) { as_s[t] = 0.f; ad_s[t] = 0.f; }
    __syncthreads();

    int cq = t & 63, nq = t >> 6;        // 4 cols x 4 nodes
    float acc[4][4] = {};
#pragma unroll 4
    for (int k = 0; k < 64; k++) {
        float4 xv = *(const float4*)&hs[k * 36 + nq * 4];
        float4 wv = *(const float4*)&Ws[k * 256 + cq * 4];
        float xa[4] = {xv.x, xv.y, xv.z, xv.w};
        float wa[4] = {wv.x, wv.y, wv.z, wv.w};
#pragma unroll
        for (int i = 0; i < 4; i++)
#pragma unroll
            for (int j = 0; j < 4; j++) acc[i][j] += xa[i] * wa[j];
    }
    int c0 = cq * 4;
    float4 s4 = *(const float4*)&att_src[c0];
    float4 d4 = *(const float4*)&att_dst[c0];
    int head = cq >> 4;
#pragma unroll
    for (int i = 0; i < 4; i++) {
        int nloc = nq * 4 + i;
        int n = n0 + nloc;
        if (n < N_NODES) {
            *(float4*)&g_hg[n * 256 + c0] =
                make_float4(acc[i][0], acc[i][1], acc[i][2], acc[i][3]);
            float sp = acc[i][0] * s4.x + acc[i][1] * s4.y + acc[i][2] * s4.z + acc[i][3] * s4.w;
            float dp = acc[i][0] * d4.x + acc[i][1] * d4.y + acc[i][2] * d4.z + acc[i][3] * d4.w;
            atomicAdd_block(&as_s[nloc * 4 + head], sp);
            atomicAdd_block(&ad_s[nloc * 4 + head], dp);
        }
    }
    __syncthreads();
    if (t < 128) {
        int n = n0 + (t >> 2);
        if (n < N_NODES) {
            float as = as_s[t], ad = ad_s[t];
            int o = n * 4 + (t & 3);
            g_asrc[o] = as; g_adst[o] = ad;
            float es = leaky(as + ad);
            g_eself[o] = es;
            g_emax[o] = es;              // self loop always present
        }
    }
}

// ---------------- GAT softmax passes (thread per edge) ----------------
__global__ void k_gat_max(const int* __restrict__ ei, int E) {
    int e = blockIdx.x * blockDim.x + threadIdx.x;
    if (e >= E) return;
    int r = ei[e], cl = ei[E + e];
    float4 s = *(const float4*)&g_asrc[r * 4];
    float4 d = *(const float4*)&g_adst[cl * 4];
    atomicMaxF(&g_emax[cl * 4 + 0], leaky(s.x + d.x));
    atomicMaxF(&g_emax[cl * 4 + 1], leaky(s.y + d.y));
    atomicMaxF(&g_emax[cl * 4 + 2], leaky(s.z + d.z));
    atomicMaxF(&g_emax[cl * 4 + 3], leaky(s.w + d.w));
}

__global__ void k_esum_init() {
    int idx = blockIdx.x * blockDim.x + threadIdx.x;
    if (idx >= N_NODES * HEADS) return;
    float ex = __expf(g_eself[idx] - g_emax[idx]);
    g_exself[idx] = ex;
    g_esum[idx] = ex;
}

__global__ void k_gat_exp(const int* __restrict__ ei, int E) {
    int e = blockIdx.x * blockDim.x + threadIdx.x;
    if (e >= E) return;
    int r = ei[e], cl = ei[E + e];
    float4 s = *(const float4*)&g_asrc[r * 4];
    float4 d = *(const float4*)&g_adst[cl * 4];
    float4 mx = *(const float4*)&g_emax[cl * 4];
    float4 ex;
    ex.x = __expf(leaky(s.x + d.x) - mx.x);
    ex.y = __expf(leaky(s.y + d.y) - mx.y);
    ex.z = __expf(leaky(s.z + d.z) - mx.z);
    ex.w = __expf(leaky(s.w + d.w) - mx.w);
    *(float4*)&g_ex[e * 4] = ex;
    red_add_v4(&g_esum[cl * 4], ex.x, ex.y, ex.z, ex.w);
}

// ex -> 0.25*alpha
__global__ void k_alpha(const int* __restrict__ ei, int E) {
    int e = blockIdx.x * blockDim.x + threadIdx.x;
    if (e >= E) return;
    int cl = ei[E + e];
    float4 ex = *(const float4*)&g_ex[e * 4];
    float4 smv = *(const float4*)&g_esum[cl * 4];
    ex.x = 0.25f * ex.x * __frcp_rn(smv.x);
    ex.y = 0.25f * ex.y * __frcp_rn(smv.y);
    ex.z = 0.25f * ex.z * __frcp_rn(smv.z);
    ex.w = 0.25f * ex.w * __frcp_rn(smv.w);
    *(float4*)&g_ex[e * 4] = ex;
}

__global__ void k_h2_init() {
    int idx = blockIdx.x * blockDim.x + threadIdx.x;
    if (idx >= NH / 4) return;
    int n = idx >> 4, q = (idx & 15) * 4;
    float4 exs = *(const float4*)&g_exself[n * 4];
    float4 smv = *(const float4*)&g_esum[n * 4];
    float a0 = 0.25f * exs.x * __frcp_rn(smv.x);
    float a1 = 0.25f * exs.y * __frcp_rn(smv.y);
    float a2 = 0.25f * exs.z * __frcp_rn(smv.z);
    float a3 = 0.25f * exs.w * __frcp_rn(smv.w);
    const float* hg = &g_hg[n * 256 + q];
    float4 h0 = *(const float4*)&hg[0];
    float4 h1v = *(const float4*)&hg[64];
    float4 h2v = *(const float4*)&hg[128];
    float4 h3v = *(const float4*)&hg[192];
    float4 o;
    o.x = a0 * h0.x + a1 * h1v.x + a2 * h2v.x + a3 * h3v.x;
    o.y = a0 * h0.y + a1 * h1v.y + a2 * h2v.y + a3 * h3v.y;
    o.z = a0 * h0.z + a1 * h1v.z + a2 * h2v.z + a3 * h3v.z;
    o.w = a0 * h0.w + a1 * h1v.w + a2 * h2v.w + a3 * h3v.w;
    ((float4*)g_h2)[idx] = o;
}

__global__ void k_gat_scatter(const int* __restrict__ ei, int E) {
    int idx = blockIdx.x * blockDim.x + threadIdx.x;
    if (idx >= E * 16) return;
    int e = idx >> 4, q = (idx & 15) * 4;
    int r = ei[e], cl = ei[E + e];
    float4 a4 = *(const float4*)&g_ex[e * 4];
    const float* hgr = &g_hg[r * 256 + q];
    float4 h0 = *(const float4*)&hgr[0];
    float4 h1v = *(const float4*)&hgr[64];
    float4 h2v = *(const float4*)&hgr[128];
    float4 h3v = *(const float4*)&hgr[192];
    red_add_v4(&g_h2[cl * 64 + q],
               a4.x * h0.x + a4.y * h1v.x + a4.z * h2v.x + a4.w * h3v.x,
               a4.x * h0.y + a4.y * h1v.y + a4.z * h2v.y + a4.w * h3v.y,
               a4.x * h0.z + a4.y * h1v.z + a4.z * h2v.z + a4.w * h3v.z,
               a4.x * h0.w + a4.y * h1v.w + a4.z * h2v.w + a4.w * h3v.w);
}

__global__ void k_gat_final(const float* __restrict__ bg) {
    int idx = blockIdx.x * blockDim.x + threadIdx.x;
    if (idx >= NH / 4) return;
    int q = (idx & 15) * 4;
    float4 h = ((const float4*)g_h2)[idx];
    float4 b = *(const float4*)&bg[q];
    h.x = fmaxf(h.x + b.x, 0.f);
    h.y = fmaxf(h.y + b.y, 0.f);
    h.z = fmaxf(h.z + b.z, 0.f);
    h.w = fmaxf(h.w + b.w, 0.f);
    ((float4*)g_h2)[idx] = h;
}

__global__ void k_sage_scatter(const int* __restrict__ ei, int E) {
    int idx = blockIdx.x * blockDim.x + threadIdx.x;
    if (idx >= E * 16) return;
    int e = idx >> 4, q = (idx & 15) * 4;
    int r = ei[e], cl = ei[E + e];
    float4 v = *(const float4*)&g_h2[r * 64 + q];
    red_add_v4(&g_sagg[cl * 64 + q], v.x, v.y, v.z, v.w);
}

// ---------------- final: emb + heads, 64 nodes/block ----------------
// smem floats: Wls 4096 | Wrs 4096 | ms 64*68 | hhs 64*68 | embs 64*64 | hw1 2*2048 | hw2 64 | hb1 64
#define FIN_SMEM ((4096 + 4096 + 4352 + 4352 + 4096 + 4096 + 64 + 64) * 4)
__global__ __launch_bounds__(256) void k_final(
    const float* __restrict__ Wl, const float* __restrict__ bl,
    const float* __restrict__ Wr,
    const float* __restrict__ a1_w, const float* __restrict__ a1_b,
    const float* __restrict__ a2_w, const float* __restrict__ a2_b,
    const float* __restrict__ r1_w, const float* __restrict__ r1_b,
    const float* __restrict__ r2_w, const float* __restrict__ r2_b,
    float* __restrict__ out) {
    extern __shared__ float sm[];
    float* Wls  = sm;                 // 4096
    float* Wrs  = Wls + 4096;         // 4096
    float* ms   = Wrs + 4096;         // [k][n] stride 68, 64 k
    float* hhs  = ms + 4352;          // [k][n] stride 68
    float* embs = hhs + 4352;         // 64 x 64
    float* hw1  = embs + 4096;        // 2 x 2048
    float* hw2  = hw1 + 4096;         // 2 x 32
    float* hb1  = hw2 + 64;           // 2 x 32
    int t = threadIdx.x;
    int n0 = blockIdx.x * 64;

#pragma unroll
    for (int i = 0; i < 4; i++) {
        ((float4*)Wls)[t + 256 * i] = ((const float4*)Wl)[t + 256 * i];
        ((float4*)Wrs)[t + 256 * i] = ((const float4*)Wr)[t + 256 * i];
    }
#pragma unroll
    for (int i = 0; i < 2; i++) {
        ((float4*)hw1)[t + 256 * i] = ((const float4*)a1_w)[t + 256 * i];
        ((float4*)(hw1 + 2048))[t + 256 * i] = ((const float4*)r1_w)[t + 256 * i];
    }
    if (t < 32) {
        hw2[t] = a2_w[t]; hw2[32 + t] = r2_w[t];
        hb1[t] = a1_b[t]; hb1[32 + t] = r1_b[t];
    }
    int nl = t & 63, kq = t >> 6;    // kq 0..3, each covers 16 k values
    if (n0 + nl < N_NODES) {
        float inv = __frcp_rn(fmaxf(g_deg[n0 + nl], 1.f));
#pragma unroll
        for (int j = 0; j < 4; j++) {
            int k0 = (kq * 4 + j) * 4;        // 0,4,...,60
            float4 v = *(const float4*)&g_sagg[(n0 + nl) * 64 + k0];
            ms[(k0 + 0) * 68 + nl] = v.x * inv;
            ms[(k0 + 1) * 68 + nl] = v.y * inv;
            ms[(k0 + 2) * 68 + nl] = v.z * inv;
            ms[(k0 + 3) * 68 + nl] = v.w * inv;
            float4 h = *(const float4*)&g_h2[(n0 + nl) * 64 + k0];
            hhs[(k0 + 0) * 68 + nl] = h.x;
            hhs[(k0 + 1) * 68 + nl] = h.y;
            hhs[(k0 + 2) * 68 + nl] = h.z;
            hhs[(k0 + 3) * 68 + nl] = h.w;
        }
    }
    __syncthreads();

    int cq = t & 15, nq = t >> 4;    // 16 col-quads x 16 node-quads = 64x64
    float4 blv = *(const float4*)&bl[cq * 4];
    float acc[4][4];
#pragma unroll
    for (int i = 0; i < 4; i++) { acc[i][0] = blv.x; acc[i][1] = blv.y; acc[i][2] = blv.z; acc[i][3] = blv.w; }
#pragma unroll 4
    for (int k = 0; k < 64; k++) {
        float4 mv = *(const float4*)&ms[k * 68 + nq * 4];
        float4 hv = *(const float4*)&hhs[k * 68 + nq * 4];
        float4 wl = *(const float4*)&Wls[k * 64 + cq * 4];
        float4 wr = *(const float4*)&Wrs[k * 64 + cq * 4];
        float ma[4] = {mv.x, mv.y, mv.z, mv.w};
        float ha[4] = {hv.x, hv.y, hv.z, hv.w};
        float wla[4] = {wl.x, wl.y, wl.z, wl.w};
        float wra[4] = {wr.x, wr.y, wr.z, wr.w};
#pragma unroll
        for (int i = 0; i < 4; i++)
#pragma unroll
            for (int j = 0; j < 4; j++)
                acc[i][j] += ma[i] * wla[j] + ha[i] * wra[j];
    }
#pragma unroll
    for (int i = 0; i < 4; i++) {
        int nloc = nq * 4 + i;
        int n = n0 + nloc;
        float4 o = make_float4(acc[i][0], acc[i][1], acc[i][2], acc[i][3]);
        *(float4*)&embs[nloc * 64 + cq * 4] = o;
        if (n < N_NODES) *(float4*)&out[(size_t)n * 64 + cq * 4] = o;
    }
    __syncthreads();

    // heads: 8 warps over 128 (node, head) groups
    int w = t >> 5, lane = t & 31;
    for (int g = w; g < 128; g += 8) {
        int n = g >> 1, hd = g & 1;
        if (n0 + n >= N_NODES) continue;
        const float* W1h = hw1 + hd * 2048;
        const float* er = embs + n * 64;
        float z = hb1[hd * 32 + lane];
#pragma unroll 16
        for (int c = 0; c < 64; c++) z += er[c] * W1h[c * 32 + lane];
        z = fmaxf(z, 0.f) * hw2[hd * 32 + lane];
#pragma unroll
        for (int o = 16; o > 0; o >>= 1) z += __shfl_down_sync(0xffffffffu, z, o);
        if (lane == 0) {
            float b2 = hd ? r2_b[0] : a2_b[0];
            float v = z + b2;
            out[NH + hd * N_NODES + n0 + n] = 1.f / (1.f + expf(-v));
        }
    }
}

// ---------------- launch ----------------
extern "C" void kernel_launch(void* const* d_in, const int* in_sizes, int n_in,
                              void* d_out, int out_size) {
    const float* x       = (const float*)d_in[0];
    const int*   ei      = (const int*)d_in[1];
    const float* W1      = (const float*)d_in[2];
    const float* b1      = (const float*)d_in[3];
    const float* Wg      = (const float*)d_in[4];
    const float* att_src = (const float*)d_in[5];
    const float* att_dst = (const float*)d_in[6];
    const float* bg      = (const float*)d_in[7];
    const float* Wl      = (const float*)d_in[8];
    const float* bl      = (const float*)d_in[9];
    const float* Wr      = (const float*)d_in[10];
    const float* a1_w    = (const float*)d_in[11];
    const float* a1_b    = (const float*)d_in[12];
    const float* a2_w    = (const float*)d_in[13];
    const float* a2_b    = (const float*)d_in[14];
    const float* r1_w    = (const float*)d_in[15];
    const float* r1_b    = (const float*)d_in[16];
    const float* r2_w    = (const float*)d_in[17];
    const float* r2_b    = (const float*)d_in[18];
    float* out = (float*)d_out;

    int E = in_sizes[1] / 2;
    const int T = 256;
    int gE    = (E + T - 1) / T;
    int gE16  = (E * 16 + T - 1) / T;
    int gNH4  = (NH / 4 + T - 1) / T;
    int gN4   = (N_NODES * HEADS + T - 1) / T;

    cudaFuncSetAttribute(k_xw,    cudaFuncAttributeMaxDynamicSharedMemorySize, XW_SMEM);
    cudaFuncSetAttribute(k_hg,    cudaFuncAttributeMaxDynamicSharedMemorySize, HG_SMEM);
    cudaFuncSetAttribute(k_final, cudaFuncAttributeMaxDynamicSharedMemorySize, FIN_SMEM);

    k_zero<<<gNH4, T>>>();
    k_xw<<<(N_NODES + 63) / 64, 256, XW_SMEM>>>(x, W1);
    k_degcnt<<<gE, T>>>(ei, E);
    k_dinv<<<(N_NODES + T - 1) / T, T>>>();
    k_gcn_scatter<<<gE16, T>>>(ei, E);
    k_gcn_final<<<gNH4, T>>>(b1);
    k_hg<<<(N_NODES + 31) / 32, 512, HG_SMEM>>>(Wg, att_src, att_dst);
    k_gat_max<<<gE, T>>>(ei, E);
    k_esum_init<<<gN4, T>>>();
    k_gat_exp<<<gE, T>>>(ei, E);
    k_alpha<<<gE, T>>>(ei, E);
    k_h2_init<<<gNH4, T>>>();
    k_gat_scatter<<<gE16, T>>>(ei, E);
    k_gat_final<<<gNH4, T>>>(bg);
    k_sage_scatter<<<gE16, T>>>(ei, E);
    k_final<<<(N_NODES + 63) / 64, 256, FIN_SMEM>>>(Wl, bl, Wr, a1_w, a1_b, a2_w, a2_b,
                                                    r1_w, r1_b, r2_w, r2_b, out);
}

// round 5
// speedup vs baseline: 2.1329x; 1.0410x over previous
#include <cuda_runtime.h>
#include <math.h>

#define N_NODES 50000
#define F_IN 128
#define H 64
#define HEADS 4
#define E_MAX 800000
#define NH (N_NODES * H)

// ---------------- scratch ----------------
__device__ float g_xw[NH];
__device__ float g_deg[N_NODES];
__device__ float g_dinv[N_NODES];
__device__ float g_h1[NH];
__device__ float g_hg[N_NODES * HEADS * H];
__device__ float g_asrc[N_NODES * HEADS];
__device__ float g_adst[N_NODES * HEADS];
__device__ float g_eself[N_NODES * HEADS];
__device__ float g_emax[N_NODES * HEADS];
__device__ float g_exself[N_NODES * HEADS];
__device__ float g_esum[N_NODES * HEADS];   // becomes 0.25/esum after k_rsum
__device__ float g_ex[E_MAX * HEADS];       // logits, then exp
__device__ float g_h2[NH];                  // GAT accum (raw: bias/relu applied by readers)
__device__ float g_sagg[NH];

__device__ __forceinline__ float leaky(float v) { return v > 0.f ? v : 0.2f * v; }

__device__ __forceinline__ void atomicMaxF(float* addr, float v) {
    if (v >= 0.f) atomicMax((int*)addr, __float_as_int(v));
    else          atomicMin((unsigned int*)addr, __float_as_uint(v));
}

__device__ __forceinline__ void red_add_v4(float* addr, float a, float b, float c, float d) {
    asm volatile("red.global.add.v4.f32 [%0], {%1, %2, %3, %4};"
                 :: "l"(addr), "f"(a), "f"(b), "f"(c), "f"(d) : "memory");
}

// ---------------- small kernels ----------------

__global__ void k_zero() {
    int i = blockIdx.x * blockDim.x + threadIdx.x;
    if (i < NH / 4) {
        ((float4*)g_h1)[i]   = make_float4(0.f, 0.f, 0.f, 0.f);
        ((float4*)g_sagg)[i] = make_float4(0.f, 0.f, 0.f, 0.f);
    }
    if (i < N_NODES / 4)
        ((float4*)g_deg)[i] = make_float4(0.f, 0.f, 0.f, 0.f);
}

__global__ void k_degcnt(const int* __restrict__ ei, int E) {
    int e = blockIdx.x * blockDim.x + threadIdx.x;
    if (e >= E) return;
    atomicAdd(&g_deg[ei[E + e]], 1.f);
}

__global__ void k_dinv() {
    int i = blockIdx.x * blockDim.x + threadIdx.x;
    if (i < N_NODES) g_dinv[i] = rsqrtf(g_deg[i] + 1.f);
}

// ---------------- dense: xw = x @ W1 (128->64), 128 nodes/block, 8x8 tiles ----------------
#define XW_SMEM ((2048 + 2112) * 16)
__global__ __launch_bounds__(128) void k_xw(const float* __restrict__ x,
                                            const float* __restrict__ W1) {
    extern __shared__ float4 sm4[];
    float4* Ws4 = sm4;           // 128 k x 16 f4
    float4* xs4 = sm4 + 2048;    // 64 k x 33 f4 (stride 132 floats)
    float* xs = (float*)xs4;
    int t = threadIdx.x;
    int n0 = blockIdx.x * 128;

#pragma unroll
    for (int i = 0; i < 16; i++) Ws4[t + 128 * i] = ((const float4*)W1)[t + 128 * i];

    int nq = t >> 3, cq = t & 7;
    float acc[8][8] = {};
    for (int ch = 0; ch < 2; ch++) {
        __syncthreads();
        int n = n0 + t;
        if (n < N_NODES) {
            const float4* xr = (const float4*)&x[(size_t)n * F_IN + ch * 64];
#pragma unroll
            for (int j = 0; j < 16; j++) {
                float4 v = xr[j];
                xs[(j * 4 + 0) * 132 + t] = v.x;
                xs[(j * 4 + 1) * 132 + t] = v.y;
                xs[(j * 4 + 2) * 132 + t] = v.z;
                xs[(j * 4 + 3) * 132 + t] = v.w;
            }
        } else {
#pragma unroll
            for (int j = 0; j < 64; j++) xs[j * 132 + t] = 0.f;
        }
        __syncthreads();
#pragma unroll 2
        for (int k = 0; k < 64; k++) {
            float4 a0 = xs4[k * 33 + nq * 2];
            float4 a1 = xs4[k * 33 + nq * 2 + 1];
            int kg = ch * 64 + k;
            float4 w0 = Ws4[kg * 16 + cq * 2];
            float4 w1 = Ws4[kg * 16 + cq * 2 + 1];
            float av[8] = {a0.x, a0.y, a0.z, a0.w, a1.x, a1.y, a1.z, a1.w};
            float wv[8] = {w0.x, w0.y, w0.z, w0.w, w1.x, w1.y, w1.z, w1.w};
#pragma unroll
            for (int i = 0; i < 8; i++)
#pragma unroll
                for (int j = 0; j < 8; j++) acc[i][j] += av[i] * wv[j];
        }
    }
#pragma unroll
    for (int i = 0; i < 8; i++) {
        int n = n0 + nq * 8 + i;
        if (n < N_NODES) {
            *(float4*)&g_xw[n * 64 + cq * 8] =
                make_float4(acc[i][0], acc[i][1], acc[i][2], acc[i][3]);
            *(float4*)&g_xw[n * 64 + cq * 8 + 4] =
                make_float4(acc[i][4], acc[i][5], acc[i][6], acc[i][7]);
        }
    }
}

// ---------------- GCN scatter ----------------
__global__ void k_gcn_scatter(const int* __restrict__ ei, int E) {
    int idx = blockIdx.x * blockDim.x + threadIdx.x;
    if (idx >= E * 16) return;
    int e = idx >> 4, q = (idx & 15) * 4;
    int r = ei[e], cl = ei[E + e];
    float nrm = g_dinv[r] * g_dinv[cl];
    float4 v = *(const float4*)&g_xw[r * 64 + q];
    red_add_v4(&g_h1[cl * 64 + q], v.x * nrm, v.y * nrm, v.z * nrm, v.w * nrm);
}

// ---------------- dense: hg = relu(gcn) @ Wg + attention dots; 64 nodes/block ----------------
// GCN bias + self-loop + relu fused into the loader.
#define HG_SMEM ((4096 + 1088) * 16)
__global__ __launch_bounds__(256) void k_hg(const float* __restrict__ Wg,
                                            const float* __restrict__ b1,
                                            const float* __restrict__ att_src,
                                            const float* __restrict__ att_dst) {
    extern __shared__ float4 sm4[];
    float4* Ws4 = sm4;           // 64 k x 64 f4 (256 floats/row)
    float4* hs4 = sm4 + 4096;    // 64 k x 17 f4 (stride 68 floats)
    float* hs = (float*)hs4;
    int t = threadIdx.x;
    int n0 = blockIdx.x * 64;

#pragma unroll
    for (int i = 0; i < 16; i++) Ws4[t + 256 * i] = ((const float4*)Wg)[t + 256 * i];

    {   // loader: 64 nodes x 4 k-quarters, fused GCN epilogue
        int nl = t & 63, kq = t >> 6;
        int n = n0 + nl;
        if (n < N_NODES) {
            float d = g_dinv[n]; float d2 = d * d;
#pragma unroll
            for (int j = 0; j < 4; j++) {
                int k0 = kq * 16 + j * 4;
                float4 hv = *(const float4*)&g_h1[n * 64 + k0];
                float4 xv = *(const float4*)&g_xw[n * 64 + k0];
                float4 bv = *(const float4*)&b1[k0];
                hs[(k0 + 0) * 68 + nl] = fmaxf(hv.x + d2 * xv.x + bv.x, 0.f);
                hs[(k0 + 1) * 68 + nl] = fmaxf(hv.y + d2 * xv.y + bv.y, 0.f);
                hs[(k0 + 2) * 68 + nl] = fmaxf(hv.z + d2 * xv.z + bv.z, 0.f);
                hs[(k0 + 3) * 68 + nl] = fmaxf(hv.w + d2 * xv.w + bv.w, 0.f);
            }
        } else {
#pragma unroll
            for (int j = 0; j < 16; j++) hs[(kq * 16 + j) * 68 + nl] = 0.f;
        }
    }
    __syncthreads();

    int nq = t >> 5, cq = t & 31;   // warp-uniform node group
    int lane = t & 31;
    float acc[8][8] = {};
#pragma unroll 2
    for (int k = 0; k < 64; k++) {
        float4 a0 = hs4[k * 17 + nq * 2];
        float4 a1 = hs4[k * 17 + nq * 2 + 1];
        float4 w0 = Ws4[k * 64 + cq * 2];
        float4 w1 = Ws4[k * 64 + cq * 2 + 1];
        float av[8] = {a0.x, a0.y, a0.z, a0.w, a1.x, a1.y, a1.z, a1.w};
        float wv[8] = {w0.x, w0.y, w0.z, w0.w, w1.x, w1.y, w1.z, w1.w};
#pragma unroll
        for (int i = 0; i < 8; i++)
#pragma unroll
            for (int j = 0; j < 8; j++) acc[i][j] += av[i] * wv[j];
    }
    int c0 = cq * 8;
    float4 s0 = *(const float4*)&att_src[c0];
    float4 s1 = *(const float4*)&att_src[c0 + 4];
    float4 d0 = *(const float4*)&att_dst[c0];
    float4 d1 = *(const float4*)&att_dst[c0 + 4];
    int head = cq >> 3;
#pragma unroll
    for (int i = 0; i < 8; i++) {
        int n = n0 + nq * 8 + i;
        bool valid = (n < N_NODES);
        if (valid) {
            *(float4*)&g_hg[(size_t)n * 256 + c0] =
                make_float4(acc[i][0], acc[i][1], acc[i][2], acc[i][3]);
            *(float4*)&g_hg[(size_t)n * 256 + c0 + 4] =
                make_float4(acc[i][4], acc[i][5], acc[i][6], acc[i][7]);
        }
        float sp = acc[i][0] * s0.x + acc[i][1] * s0.y + acc[i][2] * s0.z + acc[i][3] * s0.w
                 + acc[i][4] * s1.x + acc[i][5] * s1.y + acc[i][6] * s1.z + acc[i][7] * s1.w;
        float dp = acc[i][0] * d0.x + acc[i][1] * d0.y + acc[i][2] * d0.z + acc[i][3] * d0.w
                 + acc[i][4] * d1.x + acc[i][5] * d1.y + acc[i][6] * d1.z + acc[i][7] * d1.w;
        sp += __shfl_down_sync(0xffffffffu, sp, 4, 8);
        sp += __shfl_down_sync(0xffffffffu, sp, 2, 8);
        sp += __shfl_down_sync(0xffffffffu, sp, 1, 8);
        dp += __shfl_down_sync(0xffffffffu, dp, 4, 8);
        dp += __shfl_down_sync(0xffffffffu, dp, 2, 8);
        dp += __shfl_down_sync(0xffffffffu, dp, 1, 8);
        if ((lane & 7) == 0 && valid) {
            int o = n * 4 + head;
            g_asrc[o] = sp;
            g_adst[o] = dp;
            float es = leaky(sp + dp);
            g_eself[o] = es;
            g_emax[o] = es;             // self-loop always present
        }
    }
}

// ---------------- GAT softmax passes (thread per edge) ----------------
__global__ void k_gat_max(const int* __restrict__ ei, int E) {
    int e = blockIdx.x * blockDim.x + threadIdx.x;
    if (e >= E) return;
    int r = ei[e], cl = ei[E + e];
    float4 s = *(const float4*)&g_asrc[r * 4];
    float4 d = *(const float4*)&g_adst[cl * 4];
    float4 v;
    v.x = leaky(s.x + d.x); v.y = leaky(s.y + d.y);
    v.z = leaky(s.z + d.z); v.w = leaky(s.w + d.w);
    *(float4*)&g_ex[e * 4] = v;        // cache logits
    atomicMaxF(&g_emax[cl * 4 + 0], v.x);
    atomicMaxF(&g_emax[cl * 4 + 1], v.y);
    atomicMaxF(&g_emax[cl * 4 + 2], v.z);
    atomicMaxF(&g_emax[cl * 4 + 3], v.w);
}

__global__ void k_esum_init() {
    int idx = blockIdx.x * blockDim.x + threadIdx.x;
    if (idx >= N_NODES * HEADS) return;
    float ex = __expf(g_eself[idx] - g_emax[idx]);
    g_exself[idx] = ex;
    g_esum[idx] = ex;
}

__global__ void k_gat_exp(const int* __restrict__ ei, int E) {
    int e = blockIdx.x * blockDim.x + threadIdx.x;
    if (e >= E) return;
    int cl = ei[E + e];
    float4 v = *(const float4*)&g_ex[e * 4];   // cached logits
    float4 mx = *(const float4*)&g_emax[cl * 4];
    float4 ex;
    ex.x = __expf(v.x - mx.x); ex.y = __expf(v.y - mx.y);
    ex.z = __expf(v.z - mx.z); ex.w = __expf(v.w - mx.w);
    *(float4*)&g_ex[e * 4] = ex;
    red_add_v4(&g_esum[cl * 4], ex.x, ex.y, ex.z, ex.w);
}

// esum -> 0.25/esum (per node-head, avoids per-edge MUFU)
__global__ void k_rsum() {
    int n = blockIdx.x * blockDim.x + threadIdx.x;
    if (n >= N_NODES) return;
    float4 s = ((const float4*)g_esum)[n];
    s.x = 0.25f * __frcp_rn(s.x);
    s.y = 0.25f * __frcp_rn(s.y);
    s.z = 0.25f * __frcp_rn(s.z);
    s.w = 0.25f * __frcp_rn(s.w);
    ((float4*)g_esum)[n] = s;
}

__global__ void k_h2_init() {
    int idx = blockIdx.x * blockDim.x + threadIdx.x;
    if (idx >= NH / 4) return;
    int n = idx >> 4, q = (idx & 15) * 4;
    float4 exs = *(const float4*)&g_exself[n * 4];
    float4 rs = *(const float4*)&g_esum[n * 4];   // 0.25/esum
    float a0 = exs.x * rs.x, a1 = exs.y * rs.y, a2 = exs.z * rs.z, a3 = exs.w * rs.w;
    const float* hg = &g_hg[(size_t)n * 256 + q];
    float4 h0 = *(const float4*)&hg[0];
    float4 h1v = *(const float4*)&hg[64];
    float4 h2v = *(const float4*)&hg[128];
    float4 h3v = *(const float4*)&hg[192];
    float4 o;
    o.x = a0 * h0.x + a1 * h1v.x + a2 * h2v.x + a3 * h3v.x;
    o.y = a0 * h0.y + a1 * h1v.y + a2 * h2v.y + a3 * h3v.y;
    o.z = a0 * h0.z + a1 * h1v.z + a2 * h2v.z + a3 * h3v.z;
    o.w = a0 * h0.w + a1 * h1v.w + a2 * h2v.w + a3 * h3v.w;
    ((float4*)g_h2)[idx] = o;
}

__global__ void k_gat_scatter(const int* __restrict__ ei, int E) {
    int idx = blockIdx.x * blockDim.x + threadIdx.x;
    if (idx >= E * 16) return;
    int e = idx >> 4, q = (idx & 15) * 4;
    int r = ei[e], cl = ei[E + e];
    float4 ex = *(const float4*)&g_ex[e * 4];
    float4 rs = *(const float4*)&g_esum[cl * 4];   // 0.25/esum
    float a0 = ex.x * rs.x, a1 = ex.y * rs.y, a2 = ex.z * rs.z, a3 = ex.w * rs.w;
    const float* hgr = &g_hg[(size_t)r * 256 + q];
    float4 h0 = *(const float4*)&hgr[0];
    float4 h1v = *(const float4*)&hgr[64];
    float4 h2v = *(const float4*)&hgr[128];
    float4 h3v = *(const float4*)&hgr[192];
    red_add_v4(&g_h2[cl * 64 + q],
               a0 * h0.x + a1 * h1v.x + a2 * h2v.x + a3 * h3v.x,
               a0 * h0.y + a1 * h1v.y + a2 * h2v.y + a3 * h3v.y,
               a0 * h0.z + a1 * h1v.z + a2 * h2v.z + a3 * h3v.z,
               a0 * h0.w + a1 * h1v.w + a2 * h2v.w + a3 * h3v.w);
}

// SAGE scatter; GAT bias+relu fused at read
__global__ void k_sage_scatter(const int* __restrict__ ei, const float* __restrict__ bg, int E) {
    int idx = blockIdx.x * blockDim.x + threadIdx.x;
    if (idx >= E * 16) return;
    int e = idx >> 4, q = (idx & 15) * 4;
    int r = ei[e], cl = ei[E + e];
    float4 v = *(const float4*)&g_h2[r * 64 + q];
    float4 b = *(const float4*)&bg[q];
    red_add_v4(&g_sagg[cl * 64 + q],
               fmaxf(v.x + b.x, 0.f), fmaxf(v.y + b.y, 0.f),
               fmaxf(v.z + b.z, 0.f), fmaxf(v.w + b.w, 0.f));
}

// ---------------- final: stacked GEMM [m;h]@[Wl;Wr] + bl, then heads. 128 nodes/block ----------------
#define FIN_SMEM (5184 * 16 + 512)
__global__ __launch_bounds__(128) void k_final(
    const float* __restrict__ bl, const float* __restrict__ Wl,
    const float* __restrict__ Wr, const float* __restrict__ bg,
    const float* __restrict__ a1_w, const float* __restrict__ a1_b,
    const float* __restrict__ a2_w, const float* __restrict__ a2_b,
    const float* __restrict__ r1_w, const float* __restrict__ r1_b,
    const float* __restrict__ r2_w, const float* __restrict__ r2_b,
    float* __restrict__ out) {
    extern __shared__ float4 sm4[];
    float4* Ws4  = sm4;            // 2048 f4: rows 0-63 Wl, 64-127 Wr
    float4* xs4  = sm4 + 2048;     // 2112 f4: 64 k x 33 f4 (stride 132 floats)
    float4* hw14 = sm4 + 4160;     // 1024 f4: a1_w then r1_w
    float* tail = (float*)(sm4 + 5184);
    float* hw2 = tail;             // 2 x 32
    float* hb1 = tail + 64;        // 2 x 32
    float* xs  = (float*)xs4;
    float* hw1 = (float*)hw14;
    int t = threadIdx.x;
    int n0 = blockIdx.x * 128;

#pragma unroll
    for (int i = 0; i < 8; i++) {
        Ws4[t + 128 * i]        = ((const float4*)Wl)[t + 128 * i];
        Ws4[1024 + t + 128 * i] = ((const float4*)Wr)[t + 128 * i];
    }
#pragma unroll
    for (int i = 0; i < 4; i++) {
        hw14[t + 128 * i]       = ((const float4*)a1_w)[t + 128 * i];
        hw14[512 + t + 128 * i] = ((const float4*)r1_w)[t + 128 * i];
    }
    if (t < 32) {
        hw2[t] = a2_w[t]; hw2[32 + t] = r2_w[t];
        hb1[t] = a1_b[t]; hb1[32 + t] = r1_b[t];
    }

    int nq = t >> 3, cq = t & 7;
    float4 bl0 = *(const float4*)&bl[cq * 8];
    float4 bl1 = *(const float4*)&bl[cq * 8 + 4];
    float blv[8] = {bl0.x, bl0.y, bl0.z, bl0.w, bl1.x, bl1.y, bl1.z, bl1.w};
    float acc[8][8];
#pragma unroll
    for (int i = 0; i < 8; i++)
#pragma unroll
        for (int j = 0; j < 8; j++) acc[i][j] = blv[j];

    for (int ch = 0; ch < 2; ch++) {
        __syncthreads();
        int n = n0 + t;
        if (n < N_NODES) {
            if (ch == 0) {   // m = sagg / max(deg,1)
                float inv = __frcp_rn(fmaxf(g_deg[n], 1.f));
#pragma unroll
                for (int j = 0; j < 16; j++) {
                    float4 v = *(const float4*)&g_sagg[n * 64 + j * 4];
                    xs[(j * 4 + 0) * 132 + t] = v.x * inv;
                    xs[(j * 4 + 1) * 132 + t] = v.y * inv;
                    xs[(j * 4 + 2) * 132 + t] = v.z * inv;
                    xs[(j * 4 + 3) * 132 + t] = v.w * inv;
                }
            } else {         // h = relu(h2 + bg)
#pragma unroll
                for (int j = 0; j < 16; j++) {
                    float4 v = *(const float4*)&g_h2[n * 64 + j * 4];
                    float4 b = *(const float4*)&bg[j * 4];
                    xs[(j * 4 + 0) * 132 + t] = fmaxf(v.x + b.x, 0.f);
                    xs[(j * 4 + 1) * 132 + t] = fmaxf(v.y + b.y, 0.f);
                    xs[(j * 4 + 2) * 132 + t] = fmaxf(v.z + b.z, 0.f);
                    xs[(j * 4 + 3) * 132 + t] = fmaxf(v.w + b.w, 0.f);
                }
            }
        } else {
#pragma unroll
            for (int j = 0; j < 64; j++) xs[j * 132 + t] = 0.f;
        }
        __syncthreads();
#pragma unroll 2
        for (int k = 0; k < 64; k++) {
            float4 a0 = xs4[k * 33 + nq * 2];
            float4 a1 = xs4[k * 33 + nq * 2 + 1];
            int kg = ch * 64 + k;
            float4 w0 = Ws4[kg * 16 + cq * 2];
            float4 w1 = Ws4[kg * 16 + cq * 2 + 1];
            float av[8] = {a0.x, a0.y, a0.z, a0.w, a1.x, a1.y, a1.z, a1.w};
            float wv[8] = {w0.x, w0.y, w0.z, w0.w, w1.x, w1.y, w1.z, w1.w};
#pragma unroll
            for (int i = 0; i < 8; i++)
#pragma unroll
                for (int j = 0; j < 8; j++) acc[i][j] += av[i] * wv[j];
        }
    }
#pragma unroll
    for (int i = 0; i < 8; i++) {
        int n = n0 + nq * 8 + i;
        if (n < N_NODES) {
            *(float4*)&out[(size_t)n * 64 + cq * 8] =
                make_float4(acc[i][0], acc[i][1], acc[i][2], acc[i][3]);
            *(float4*)&out[(size_t)n * 64 + cq * 8 + 4] =
                make_float4(acc[i][4], acc[i][5], acc[i][6], acc[i][7]);
        }
    }
    __syncthreads();   // emb visible block-wide (global, same block)

    // heads: warp 0-1 -> anomaly, 2-3 -> risk; each warp 64 nodes
    int w = t >> 5, lane = t & 31;
    int hd = w >> 1, half = w & 1;
    float w1r[64];
#pragma unroll
    for (int c = 0; c < 64; c++) w1r[c] = hw1[hd * 2048 + c * 32 + lane];
    float w2v = hw2[hd * 32 + lane];
    float b1v = hb1[hd * 32 + lane];
    float b2 = hd ? r2_b[0] : a2_b[0];
    for (int ln = half * 64; ln < half * 64 + 64; ln++) {
        int n = n0 + ln;
        if (n >= N_NODES) break;
        float2 ep = *(const float2*)&out[(size_t)n * 64 + lane * 2];
        float z = b1v;
#pragma unroll
        for (int c = 0; c < 64; c++) {
            float ec = __shfl_sync(0xffffffffu, (c & 1) ? ep.y : ep.x, c >> 1);
            z += ec * w1r[c];
        }
        z = fmaxf(z, 0.f) * w2v;
#pragma unroll
        for (int off = 16; off > 0; off >>= 1)
            z += __shfl_down_sync(0xffffffffu, z, off);
        if (lane == 0)
            out[NH + hd * N_NODES + n] = 1.f / (1.f + expf(-z));
    }
}

// ---------------- launch ----------------
extern "C" void kernel_launch(void* const* d_in, const int* in_sizes, int n_in,
                              void* d_out, int out_size) {
    const float* x       = (const float*)d_in[0];
    const int*   ei      = (const int*)d_in[1];
    const float* W1      = (const float*)d_in[2];
    const float* b1      = (const float*)d_in[3];
    const float* Wg      = (const float*)d_in[4];
    const float* att_src = (const float*)d_in[5];
    const float* att_dst = (const float*)d_in[6];
    const float* bg      = (const float*)d_in[7];
    const float* Wl      = (const float*)d_in[8];
    const float* bl      = (const float*)d_in[9];
    const float* Wr      = (const float*)d_in[10];
    const float* a1_w    = (const float*)d_in[11];
    const float* a1_b    = (const float*)d_in[12];
    const float* a2_w    = (const float*)d_in[13];
    const float* a2_b    = (const float*)d_in[14];
    const float* r1_w    = (const float*)d_in[15];
    const float* r1_b    = (const float*)d_in[16];
    const float* r2_w    = (const float*)d_in[17];
    const float* r2_b    = (const float*)d_in[18];
    float* out = (float*)d_out;

    int E = in_sizes[1] / 2;
    const int T = 256;
    int gE    = (E + T - 1) / T;
    int gE16  = (E * 16 + T - 1) / T;
    int gNH4  = (NH / 4 + T - 1) / T;
    int gN4   = (N_NODES * HEADS + T - 1) / T;
    int gN    = (N_NODES + T - 1) / T;

    cudaFuncSetAttribute(k_xw,    cudaFuncAttributeMaxDynamicSharedMemorySize, XW_SMEM);
    cudaFuncSetAttribute(k_hg,    cudaFuncAttributeMaxDynamicSharedMemorySize, HG_SMEM);
    cudaFuncSetAttribute(k_final, cudaFuncAttributeMaxDynamicSharedMemorySize, FIN_SMEM);

    k_zero<<<gNH4, T>>>();
    k_xw<<<(N_NODES + 127) / 128, 128, XW_SMEM>>>(x, W1);
    k_degcnt<<<gE, T>>>(ei, E);
    k_dinv<<<gN, T>>>();
    k_gcn_scatter<<<gE16, T>>>(ei, E);
    k_hg<<<(N_NODES + 63) / 64, 256, HG_SMEM>>>(Wg, b1, att_src, att_dst);
    k_gat_max<<<gE, T>>>(ei, E);
    k_esum_init<<<gN4, T>>>();
    k_gat_exp<<<gE, T>>>(ei, E);
    k_rsum<<<gN, T>>>();
    k_h2_init<<<gNH4, T>>>();
    k_gat_scatter<<<gE16, T>>>(ei, E);
    k_sage_scatter<<<gE16, T>>>(ei, bg, E);
    k_final<<<(N_NODES + 127) / 128, 128, FIN_SMEM>>>(bl, Wl, Wr, bg,
                                                      a1_w, a1_b, a2_w, a2_b,
                                                      r1_w, r1_b, r2_w, r2_b, out);
}